// round 11
// baseline (speedup 1.0000x reference)
#include <cuda_runtime.h>

#define BATCH 16
#define IMG_H 352
#define IMG_W 1216
#define IMG_HW (IMG_H * IMG_W)
#define SEG 16
#define SEGS_PER_ROW (IMG_W / SEG)           /* 76    */
#define TASKS_PER_IMG (IMG_H * SEGS_PER_ROW) /* 26752 */
#define NB1 52
#define TPB 256

// Scratch (no allocations allowed -> device globals)
__device__ float g_part1[BATCH * NB1 * 3];
__device__ float g_scale[2 * BATCH + 1];   // [0..15]=scale_p, [16..31]=scale_t, [32]=total_mask
__device__ float g_part2[BATCH * NB1];

struct SCol { float s0, s1, s2, c; };      // sorted column + original center

__device__ __forceinline__ void cswap(float& a, float& b) {
    float t = fminf(a, b); b = fmaxf(a, b); a = t;
}

__device__ __forceinline__ SCol make_col(float u, float v, float w) {
    SCol r; r.c = v;
    cswap(u, v); cswap(v, w); cswap(u, v);
    r.s0 = u; r.s1 = v; r.s2 = w;
    return r;
}

__device__ __forceinline__ float med3f(float a, float b, float c) {
    return fmaxf(fminf(a, b), fminf(fmaxf(a, b), c));
}

// Exact 3x3 median from 3 column-sorted triples:
// med9 = med3( max(lows), med3(mids), min(highs) )
__device__ __forceinline__ float merge_med(const SCol& A, const SCol& B, const SCol& C) {
    float lo = fmaxf(fmaxf(A.s0, B.s0), C.s0);
    float mi = med3f(A.s1, B.s1, C.s1);
    float hi = fminf(fminf(A.s2, B.s2), C.s2);
    return med3f(lo, mi, hi);
}

__device__ __forceinline__ SCol load_col(const float* r0, const float* r1, const float* r2,
                                         int x, bool up, bool dn) {
    float u = up ? __ldg(r0 + x) : 0.f;
    float v = __ldg(r1 + x);
    float w = dn ? __ldg(r2 + x) : 0.f;
    return make_col(u, v, w);
}

__device__ __forceinline__ float4 ld4z(const float* p, bool valid) {
    if (valid) return __ldg((const float4*)p);
    return make_float4(0.f, 0.f, 0.f, 0.f);
}

// ---------------------------------------------------------------------------
// Pass 1: per-image sums of mask, mask*|pred_contrast|, mask*|target_contrast|
// ---------------------------------------------------------------------------
__global__ void __launch_bounds__(TPB) pass1_kernel(const float* __restrict__ pred,
                                                    const float* __restrict__ targ,
                                                    const float* __restrict__ mask) {
    const int b = blockIdx.y;
    const float* P = pred + (size_t)b * IMG_HW;
    const float* T = targ + (size_t)b * IMG_HW;
    const float* M = mask + (size_t)b * IMG_HW;

    float s_m = 0.f, s_p = 0.f, s_t = 0.f;

    for (int task = blockIdx.x * TPB + threadIdx.x; task < TASKS_PER_IMG; task += NB1 * TPB) {
        const int y  = task / SEGS_PER_ROW;
        const int x0 = (task - y * SEGS_PER_ROW) * SEG;
        const bool up = (y > 0), dn = (y < IMG_H - 1);
        const float* p1 = P + y * IMG_W; const float* p0 = p1 - IMG_W; const float* p2 = p1 + IMG_W;
        const float* t1 = T + y * IMG_W; const float* t0 = t1 - IMG_W; const float* t2 = t1 + IMG_W;
        const float* m1 = M + y * IMG_W;

        // Preload the 16 mask values for this segment as 4x float4
        // (constant indexing after full unroll -> stays in registers).
        float mv[SEG];
#pragma unroll
        for (int g = 0; g < SEG / 4; g++) {
            float4 m4 = __ldg((const float4*)(m1 + x0 + 4 * g));
            mv[4 * g + 0] = m4.x; mv[4 * g + 1] = m4.y;
            mv[4 * g + 2] = m4.z; mv[4 * g + 3] = m4.w;
        }

        SCol pa, pb, ta, tb;
        if (x0 > 0) { pa = load_col(p0, p1, p2, x0 - 1, up, dn);
                      ta = load_col(t0, t1, t2, x0 - 1, up, dn); }
        else        { pa = make_col(0.f, 0.f, 0.f); ta = make_col(0.f, 0.f, 0.f); }

#pragma unroll
        for (int g = 0; g < SEG / 4; g++) {
            const int xg = x0 + 4 * g;
            float4 A  = ld4z(p0 + xg, up);
            float4 Bv = __ldg((const float4*)(p1 + xg));
            float4 C  = ld4z(p2 + xg, dn);
            float4 D  = ld4z(t0 + xg, up);
            float4 E  = __ldg((const float4*)(t1 + xg));
            float4 F  = ld4z(t2 + xg, dn);
            float a4[4] = {A.x, A.y, A.z, A.w}, b4[4] = {Bv.x, Bv.y, Bv.z, Bv.w};
            float c4[4] = {C.x, C.y, C.z, C.w}, d4[4] = {D.x, D.y, D.z, D.w};
            float e4[4] = {E.x, E.y, E.z, E.w}, f4[4] = {F.x, F.y, F.z, F.w};
#pragma unroll
            for (int j = 0; j < 4; j++) {
                SCol pn = make_col(a4[j], b4[j], c4[j]);
                SCol tn = make_col(d4[j], e4[j], f4[j]);
                if (!(g == 0 && j == 0)) {
                    float pc = pb.c - merge_med(pa, pb, pn);
                    float tc = tb.c - merge_med(ta, tb, tn);
                    float m  = mv[4 * g + j - 1];   // emitted pixel xg+j-1
                    s_m += m;
                    s_p = fmaf(m, fabsf(pc), s_p);
                    s_t = fmaf(m, fabsf(tc), s_t);
                    pa = pb; ta = tb;
                }
                pb = pn; tb = tn;
            }
        }
        {   // trailing halo column -> pixel x0+SEG-1
            const int xl = x0 + SEG;
            const bool inb = (xl < IMG_W);
            SCol pn = inb ? load_col(p0, p1, p2, xl, up, dn) : make_col(0.f, 0.f, 0.f);
            SCol tn = inb ? load_col(t0, t1, t2, xl, up, dn) : make_col(0.f, 0.f, 0.f);
            float pc = pb.c - merge_med(pa, pb, pn);
            float tc = tb.c - merge_med(ta, tb, tn);
            float m  = mv[SEG - 1];
            s_m += m;
            s_p = fmaf(m, fabsf(pc), s_p);
            s_t = fmaf(m, fabsf(tc), s_t);
        }
    }

    // block reduce (deterministic)
    const unsigned FULL = 0xffffffffu;
    __shared__ float shm[3][TPB / 32];
#pragma unroll
    for (int o = 16; o; o >>= 1) {
        s_m += __shfl_down_sync(FULL, s_m, o);
        s_p += __shfl_down_sync(FULL, s_p, o);
        s_t += __shfl_down_sync(FULL, s_t, o);
    }
    const int warp = threadIdx.x >> 5, lane = threadIdx.x & 31;
    if (lane == 0) { shm[0][warp] = s_m; shm[1][warp] = s_p; shm[2][warp] = s_t; }
    __syncthreads();
    if (threadIdx.x < 32) {
        float vm = (lane < TPB / 32) ? shm[0][lane] : 0.f;
        float vp = (lane < TPB / 32) ? shm[1][lane] : 0.f;
        float vt = (lane < TPB / 32) ? shm[2][lane] : 0.f;
#pragma unroll
        for (int o = 4; o; o >>= 1) {
            vm += __shfl_down_sync(FULL, vm, o);
            vp += __shfl_down_sync(FULL, vp, o);
            vt += __shfl_down_sync(FULL, vt, o);
        }
        if (lane == 0) {
            const int base = (b * NB1 + blockIdx.x) * 3;
            g_part1[base + 0] = vm;
            g_part1[base + 1] = vp;
            g_part1[base + 2] = vt;
        }
    }
}

// ---------------------------------------------------------------------------
// Pass 2: reduce partials (double), compute per-image scales + total mask
// ---------------------------------------------------------------------------
__global__ void __launch_bounds__(TPB) pass2_kernel() {
    __shared__ double sh[BATCH * 3];
    const int warp = threadIdx.x >> 5, lane = threadIdx.x & 31;
    const unsigned FULL = 0xffffffffu;
    for (int task = warp; task < BATCH * 3; task += TPB / 32) {
        const int b = task / 3, c = task - 3 * b;
        double s = 0.0;
        for (int i = lane; i < NB1; i += 32) s += (double)g_part1[(b * NB1 + i) * 3 + c];
#pragma unroll
        for (int o = 16; o; o >>= 1) s += __shfl_down_sync(FULL, s, o);
        if (lane == 0) sh[task] = s;
    }
    __syncthreads();
    if (threadIdx.x < BATCH) {
        const int b = threadIdx.x;
        double denom = sh[b * 3 + 0];
        g_scale[b]         = (float)(denom / sh[b * 3 + 1]);
        g_scale[BATCH + b] = (float)(denom / sh[b * 3 + 2]);
    }
    __syncthreads();
    if (threadIdx.x == 0) {
        double tm = 0.0;
        for (int b = 0; b < BATCH; b++) tm += sh[b * 3];
        g_scale[2 * BATCH] = (float)tm;
    }
}

// ---------------------------------------------------------------------------
// Pass 3: sum |pc*scale_p - tc*scale_t| (no mask needed here)
// ---------------------------------------------------------------------------
__global__ void __launch_bounds__(TPB) pass3_kernel(const float* __restrict__ pred,
                                                    const float* __restrict__ targ) {
    const int b = blockIdx.y;
    const float* P = pred + (size_t)b * IMG_HW;
    const float* T = targ + (size_t)b * IMG_HW;
    const float sp = g_scale[b];
    const float st = g_scale[BATCH + b];

    float s = 0.f;

    for (int task = blockIdx.x * TPB + threadIdx.x; task < TASKS_PER_IMG; task += NB1 * TPB) {
        const int y  = task / SEGS_PER_ROW;
        const int x0 = (task - y * SEGS_PER_ROW) * SEG;
        const bool up = (y > 0), dn = (y < IMG_H - 1);
        const float* p1 = P + y * IMG_W; const float* p0 = p1 - IMG_W; const float* p2 = p1 + IMG_W;
        const float* t1 = T + y * IMG_W; const float* t0 = t1 - IMG_W; const float* t2 = t1 + IMG_W;

        SCol pa, pb, ta, tb;
        if (x0 > 0) { pa = load_col(p0, p1, p2, x0 - 1, up, dn);
                      ta = load_col(t0, t1, t2, x0 - 1, up, dn); }
        else        { pa = make_col(0.f, 0.f, 0.f); ta = make_col(0.f, 0.f, 0.f); }

#pragma unroll
        for (int g = 0; g < SEG / 4; g++) {
            const int xg = x0 + 4 * g;
            float4 A  = ld4z(p0 + xg, up);
            float4 Bv = __ldg((const float4*)(p1 + xg));
            float4 C  = ld4z(p2 + xg, dn);
            float4 D  = ld4z(t0 + xg, up);
            float4 E  = __ldg((const float4*)(t1 + xg));
            float4 F  = ld4z(t2 + xg, dn);
            float a4[4] = {A.x, A.y, A.z, A.w}, b4[4] = {Bv.x, Bv.y, Bv.z, Bv.w};
            float c4[4] = {C.x, C.y, C.z, C.w}, d4[4] = {D.x, D.y, D.z, D.w};
            float e4[4] = {E.x, E.y, E.z, E.w}, f4[4] = {F.x, F.y, F.z, F.w};
#pragma unroll
            for (int j = 0; j < 4; j++) {
                SCol pn = make_col(a4[j], b4[j], c4[j]);
                SCol tn = make_col(d4[j], e4[j], f4[j]);
                if (!(g == 0 && j == 0)) {
                    float pc = pb.c - merge_med(pa, pb, pn);
                    float tc = tb.c - merge_med(ta, tb, tn);
                    s += fabsf(fmaf(pc, sp, -(tc * st)));
                    pa = pb; ta = tb;
                }
                pb = pn; tb = tn;
            }
        }
        {
            const int xl = x0 + SEG;
            const bool inb = (xl < IMG_W);
            SCol pn = inb ? load_col(p0, p1, p2, xl, up, dn) : make_col(0.f, 0.f, 0.f);
            SCol tn = inb ? load_col(t0, t1, t2, xl, up, dn) : make_col(0.f, 0.f, 0.f);
            float pc = pb.c - merge_med(pa, pb, pn);
            float tc = tb.c - merge_med(ta, tb, tn);
            s += fabsf(fmaf(pc, sp, -(tc * st)));
        }
    }

    const unsigned FULL = 0xffffffffu;
    __shared__ float shm[TPB / 32];
#pragma unroll
    for (int o = 16; o; o >>= 1) s += __shfl_down_sync(FULL, s, o);
    const int warp = threadIdx.x >> 5, lane = threadIdx.x & 31;
    if (lane == 0) shm[warp] = s;
    __syncthreads();
    if (threadIdx.x < 32) {
        float v = (lane < TPB / 32) ? shm[lane] : 0.f;
#pragma unroll
        for (int o = 4; o; o >>= 1) v += __shfl_down_sync(FULL, v, o);
        if (lane == 0) g_part2[b * NB1 + blockIdx.x] = v;
    }
}

// ---------------------------------------------------------------------------
// Pass 4: final scalar = sum(loss partials) / total_mask
// ---------------------------------------------------------------------------
__global__ void __launch_bounds__(TPB) pass4_kernel(float* __restrict__ out) {
    const unsigned FULL = 0xffffffffu;
    double s = 0.0;
    for (int i = threadIdx.x; i < BATCH * NB1; i += TPB) s += (double)g_part2[i];
#pragma unroll
    for (int o = 16; o; o >>= 1) s += __shfl_down_sync(FULL, s, o);
    __shared__ double sh[TPB / 32];
    const int warp = threadIdx.x >> 5, lane = threadIdx.x & 31;
    if (lane == 0) sh[warp] = s;
    __syncthreads();
    if (threadIdx.x < 32) {
        double v = (lane < TPB / 32) ? sh[lane] : 0.0;
#pragma unroll
        for (int o = 4; o; o >>= 1) v += __shfl_down_sync(FULL, v, o);
        if (lane == 0) out[0] = (float)(v / (double)g_scale[2 * BATCH]);
    }
}

// ---------------------------------------------------------------------------
extern "C" void kernel_launch(void* const* d_in, const int* in_sizes, int n_in,
                              void* d_out, int out_size) {
    const float* pred = (const float*)d_in[0];
    const float* targ = (const float*)d_in[1];
    const float* mask = (const float*)d_in[2];
    float* out = (float*)d_out;

    dim3 grid(NB1, BATCH);
    pass1_kernel<<<grid, TPB>>>(pred, targ, mask);
    pass2_kernel<<<1, TPB>>>();
    pass3_kernel<<<grid, TPB>>>(pred, targ);
    pass4_kernel<<<1, TPB>>>(out);
}

// round 16
// speedup vs baseline: 1.0030x; 1.0030x over previous
#include <cuda_runtime.h>

#define BATCH 16
#define IMG_H 352
#define IMG_W 1216
#define IMG_HW (IMG_H * IMG_W)
#define SEG 16
#define SEGS_PER_ROW (IMG_W / SEG)           /* 76    */
#define TASKS_PER_IMG (IMG_H * SEGS_PER_ROW) /* 26752 */
#define NB1 52
#define TPB 256
#define TOTAL_BLOCKS (NB1 * BATCH)           /* 832   */

// Scratch (no allocations allowed -> device globals)
__device__ float g_part1[BATCH * NB1 * 3];
__device__ float g_scale[2 * BATCH + 1];   // [0..15]=scale_p, [16..31]=scale_t, [32]=total_mask
__device__ float g_part2[BATCH * NB1];
__device__ unsigned int g_cnt1 = 0;
__device__ unsigned int g_cnt2 = 0;

struct SCol { float s0, s1, s2, c; };      // sorted column + original center

__device__ __forceinline__ void cswap(float& a, float& b) {
    float t = fminf(a, b); b = fmaxf(a, b); a = t;
}

__device__ __forceinline__ SCol make_col(float u, float v, float w) {
    SCol r; r.c = v;
    cswap(u, v); cswap(v, w); cswap(u, v);
    r.s0 = u; r.s1 = v; r.s2 = w;
    return r;
}

__device__ __forceinline__ float med3f(float a, float b, float c) {
    return fmaxf(fminf(a, b), fminf(fmaxf(a, b), c));
}

// Exact 3x3 median from 3 column-sorted triples:
// med9 = med3( max(lows), med3(mids), min(highs) )
__device__ __forceinline__ float merge_med(const SCol& A, const SCol& B, const SCol& C) {
    float lo = fmaxf(fmaxf(A.s0, B.s0), C.s0);
    float mi = med3f(A.s1, B.s1, C.s1);
    float hi = fminf(fminf(A.s2, B.s2), C.s2);
    return med3f(lo, mi, hi);
}

__device__ __forceinline__ SCol load_col(const float* r0, const float* r1, const float* r2,
                                         int x, bool up, bool dn) {
    float u = up ? __ldg(r0 + x) : 0.f;
    float v = __ldg(r1 + x);
    float w = dn ? __ldg(r2 + x) : 0.f;
    return make_col(u, v, w);
}

__device__ __forceinline__ float4 ld4z(const float* p, bool valid) {
    if (valid) return __ldg((const float4*)p);
    return make_float4(0.f, 0.f, 0.f, 0.f);
}

// ---------------------------------------------------------------------------
// Pass 1 (+ fused pass 2 in last block):
// per-image sums of mask, mask*|pred_contrast|, mask*|target_contrast|,
// then the last block to finish reduces partials (double) and emits
// per-image scales + total mask.
// ---------------------------------------------------------------------------
__global__ void __launch_bounds__(TPB) pass1_kernel(const float* __restrict__ pred,
                                                    const float* __restrict__ targ,
                                                    const float* __restrict__ mask) {
    const int b = blockIdx.y;
    const float* P = pred + (size_t)b * IMG_HW;
    const float* T = targ + (size_t)b * IMG_HW;
    const float* M = mask + (size_t)b * IMG_HW;

    float s_m = 0.f, s_p = 0.f, s_t = 0.f;

    for (int task = blockIdx.x * TPB + threadIdx.x; task < TASKS_PER_IMG; task += NB1 * TPB) {
        const int y  = task / SEGS_PER_ROW;
        const int x0 = (task - y * SEGS_PER_ROW) * SEG;
        const bool up = (y > 0), dn = (y < IMG_H - 1);
        const float* p1 = P + y * IMG_W; const float* p0 = p1 - IMG_W; const float* p2 = p1 + IMG_W;
        const float* t1 = T + y * IMG_W; const float* t0 = t1 - IMG_W; const float* t2 = t1 + IMG_W;
        const float* m1 = M + y * IMG_W;

        // Preload 16 mask values as 4x float4 (constant indexing -> registers).
        float mv[SEG];
#pragma unroll
        for (int g = 0; g < SEG / 4; g++) {
            float4 m4 = __ldg((const float4*)(m1 + x0 + 4 * g));
            mv[4 * g + 0] = m4.x; mv[4 * g + 1] = m4.y;
            mv[4 * g + 2] = m4.z; mv[4 * g + 3] = m4.w;
        }

        SCol pa, pb, ta, tb;
        if (x0 > 0) { pa = load_col(p0, p1, p2, x0 - 1, up, dn);
                      ta = load_col(t0, t1, t2, x0 - 1, up, dn); }
        else        { pa = make_col(0.f, 0.f, 0.f); ta = make_col(0.f, 0.f, 0.f); }

#pragma unroll
        for (int g = 0; g < SEG / 4; g++) {
            const int xg = x0 + 4 * g;
            float4 A  = ld4z(p0 + xg, up);
            float4 Bv = __ldg((const float4*)(p1 + xg));
            float4 C  = ld4z(p2 + xg, dn);
            float4 D  = ld4z(t0 + xg, up);
            float4 E  = __ldg((const float4*)(t1 + xg));
            float4 F  = ld4z(t2 + xg, dn);
            float a4[4] = {A.x, A.y, A.z, A.w}, b4[4] = {Bv.x, Bv.y, Bv.z, Bv.w};
            float c4[4] = {C.x, C.y, C.z, C.w}, d4[4] = {D.x, D.y, D.z, D.w};
            float e4[4] = {E.x, E.y, E.z, E.w}, f4[4] = {F.x, F.y, F.z, F.w};
#pragma unroll
            for (int j = 0; j < 4; j++) {
                SCol pn = make_col(a4[j], b4[j], c4[j]);
                SCol tn = make_col(d4[j], e4[j], f4[j]);
                if (!(g == 0 && j == 0)) {
                    float pc = pb.c - merge_med(pa, pb, pn);
                    float tc = tb.c - merge_med(ta, tb, tn);
                    float m  = mv[4 * g + j - 1];   // emitted pixel xg+j-1
                    s_m += m;
                    s_p = fmaf(m, fabsf(pc), s_p);
                    s_t = fmaf(m, fabsf(tc), s_t);
                    pa = pb; ta = tb;
                }
                pb = pn; tb = tn;
            }
        }
        {   // trailing halo column -> pixel x0+SEG-1
            const int xl = x0 + SEG;
            const bool inb = (xl < IMG_W);
            SCol pn = inb ? load_col(p0, p1, p2, xl, up, dn) : make_col(0.f, 0.f, 0.f);
            SCol tn = inb ? load_col(t0, t1, t2, xl, up, dn) : make_col(0.f, 0.f, 0.f);
            float pc = pb.c - merge_med(pa, pb, pn);
            float tc = tb.c - merge_med(ta, tb, tn);
            float m  = mv[SEG - 1];
            s_m += m;
            s_p = fmaf(m, fabsf(pc), s_p);
            s_t = fmaf(m, fabsf(tc), s_t);
        }
    }

    // block reduce (deterministic)
    const unsigned FULL = 0xffffffffu;
    __shared__ float shm[3][TPB / 32];
#pragma unroll
    for (int o = 16; o; o >>= 1) {
        s_m += __shfl_down_sync(FULL, s_m, o);
        s_p += __shfl_down_sync(FULL, s_p, o);
        s_t += __shfl_down_sync(FULL, s_t, o);
    }
    const int warp = threadIdx.x >> 5, lane = threadIdx.x & 31;
    if (lane == 0) { shm[0][warp] = s_m; shm[1][warp] = s_p; shm[2][warp] = s_t; }
    __syncthreads();
    if (threadIdx.x < 32) {
        float vm = (lane < TPB / 32) ? shm[0][lane] : 0.f;
        float vp = (lane < TPB / 32) ? shm[1][lane] : 0.f;
        float vt = (lane < TPB / 32) ? shm[2][lane] : 0.f;
#pragma unroll
        for (int o = 4; o; o >>= 1) {
            vm += __shfl_down_sync(FULL, vm, o);
            vp += __shfl_down_sync(FULL, vp, o);
            vt += __shfl_down_sync(FULL, vt, o);
        }
        if (lane == 0) {
            const int base = (b * NB1 + blockIdx.x) * 3;
            g_part1[base + 0] = vm;
            g_part1[base + 1] = vp;
            g_part1[base + 2] = vt;
        }
    }

    // ---- fused pass 2: last block reduces partials and computes scales ----
    __shared__ bool s_last;
    __syncthreads();                 // g_part1 writes by thread 0 complete
    if (threadIdx.x == 0) {
        __threadfence();             // publish this block's partials
        unsigned v = atomicAdd(&g_cnt1, 1u);
        s_last = (v == TOTAL_BLOCKS - 1);
    }
    __syncthreads();
    if (!s_last) return;
    __threadfence();                 // acquire: see all blocks' partials

    __shared__ double sh[BATCH * 3];
    for (int task = warp; task < BATCH * 3; task += TPB / 32) {
        const int bb = task / 3, c = task - 3 * bb;
        double s = 0.0;
        for (int i = lane; i < NB1; i += 32) s += (double)g_part1[(bb * NB1 + i) * 3 + c];
#pragma unroll
        for (int o = 16; o; o >>= 1) s += __shfl_down_sync(FULL, s, o);
        if (lane == 0) sh[task] = s;
    }
    __syncthreads();
    if (threadIdx.x < BATCH) {
        const int bb = threadIdx.x;
        double denom = sh[bb * 3 + 0];
        g_scale[bb]         = (float)(denom / sh[bb * 3 + 1]);
        g_scale[BATCH + bb] = (float)(denom / sh[bb * 3 + 2]);
    }
    if (threadIdx.x == TPB - 1) {
        double tm = 0.0;
        for (int bb = 0; bb < BATCH; bb++) tm += sh[bb * 3];
        g_scale[2 * BATCH] = (float)tm;
        g_cnt1 = 0;                  // reset ticket for next graph replay
    }
}

// ---------------------------------------------------------------------------
// Pass 3 (+ fused pass 4 in last block):
// sum |pc*scale_p - tc*scale_t|; last block produces final scalar.
// ---------------------------------------------------------------------------
__global__ void __launch_bounds__(TPB) pass3_kernel(const float* __restrict__ pred,
                                                    const float* __restrict__ targ,
                                                    float* __restrict__ out) {
    const int b = blockIdx.y;
    const float* P = pred + (size_t)b * IMG_HW;
    const float* T = targ + (size_t)b * IMG_HW;
    const float sp = g_scale[b];
    const float st = g_scale[BATCH + b];

    float s = 0.f;

    for (int task = blockIdx.x * TPB + threadIdx.x; task < TASKS_PER_IMG; task += NB1 * TPB) {
        const int y  = task / SEGS_PER_ROW;
        const int x0 = (task - y * SEGS_PER_ROW) * SEG;
        const bool up = (y > 0), dn = (y < IMG_H - 1);
        const float* p1 = P + y * IMG_W; const float* p0 = p1 - IMG_W; const float* p2 = p1 + IMG_W;
        const float* t1 = T + y * IMG_W; const float* t0 = t1 - IMG_W; const float* t2 = t1 + IMG_W;

        SCol pa, pb, ta, tb;
        if (x0 > 0) { pa = load_col(p0, p1, p2, x0 - 1, up, dn);
                      ta = load_col(t0, t1, t2, x0 - 1, up, dn); }
        else        { pa = make_col(0.f, 0.f, 0.f); ta = make_col(0.f, 0.f, 0.f); }

#pragma unroll
        for (int g = 0; g < SEG / 4; g++) {
            const int xg = x0 + 4 * g;
            float4 A  = ld4z(p0 + xg, up);
            float4 Bv = __ldg((const float4*)(p1 + xg));
            float4 C  = ld4z(p2 + xg, dn);
            float4 D  = ld4z(t0 + xg, up);
            float4 E  = __ldg((const float4*)(t1 + xg));
            float4 F  = ld4z(t2 + xg, dn);
            float a4[4] = {A.x, A.y, A.z, A.w}, b4[4] = {Bv.x, Bv.y, Bv.z, Bv.w};
            float c4[4] = {C.x, C.y, C.z, C.w}, d4[4] = {D.x, D.y, D.z, D.w};
            float e4[4] = {E.x, E.y, E.z, E.w}, f4[4] = {F.x, F.y, F.z, F.w};
#pragma unroll
            for (int j = 0; j < 4; j++) {
                SCol pn = make_col(a4[j], b4[j], c4[j]);
                SCol tn = make_col(d4[j], e4[j], f4[j]);
                if (!(g == 0 && j == 0)) {
                    float pc = pb.c - merge_med(pa, pb, pn);
                    float tc = tb.c - merge_med(ta, tb, tn);
                    s += fabsf(fmaf(pc, sp, -(tc * st)));
                    pa = pb; ta = tb;
                }
                pb = pn; tb = tn;
            }
        }
        {
            const int xl = x0 + SEG;
            const bool inb = (xl < IMG_W);
            SCol pn = inb ? load_col(p0, p1, p2, xl, up, dn) : make_col(0.f, 0.f, 0.f);
            SCol tn = inb ? load_col(t0, t1, t2, xl, up, dn) : make_col(0.f, 0.f, 0.f);
            float pc = pb.c - merge_med(pa, pb, pn);
            float tc = tb.c - merge_med(ta, tb, tn);
            s += fabsf(fmaf(pc, sp, -(tc * st)));
        }
    }

    const unsigned FULL = 0xffffffffu;
    __shared__ float shm[TPB / 32];
#pragma unroll
    for (int o = 16; o; o >>= 1) s += __shfl_down_sync(FULL, s, o);
    const int warp = threadIdx.x >> 5, lane = threadIdx.x & 31;
    if (lane == 0) shm[warp] = s;
    __syncthreads();
    if (threadIdx.x < 32) {
        float v = (lane < TPB / 32) ? shm[lane] : 0.f;
#pragma unroll
        for (int o = 4; o; o >>= 1) v += __shfl_down_sync(FULL, v, o);
        if (lane == 0) g_part2[b * NB1 + blockIdx.x] = v;
    }

    // ---- fused pass 4: last block reduces loss partials to the scalar ----
    __shared__ bool s_last;
    __syncthreads();
    if (threadIdx.x == 0) {
        __threadfence();
        unsigned v = atomicAdd(&g_cnt2, 1u);
        s_last = (v == TOTAL_BLOCKS - 1);
    }
    __syncthreads();
    if (!s_last) return;
    __threadfence();

    double sd = 0.0;
    for (int i = threadIdx.x; i < BATCH * NB1; i += TPB) sd += (double)g_part2[i];
#pragma unroll
    for (int o = 16; o; o >>= 1) sd += __shfl_down_sync(FULL, sd, o);
    __shared__ double shd[TPB / 32];
    if (lane == 0) shd[warp] = sd;
    __syncthreads();
    if (threadIdx.x < 32) {
        double v = (lane < TPB / 32) ? shd[lane] : 0.0;
#pragma unroll
        for (int o = 4; o; o >>= 1) v += __shfl_down_sync(FULL, v, o);
        if (lane == 0) {
            out[0] = (float)(v / (double)g_scale[2 * BATCH]);
            g_cnt2 = 0;              // reset ticket for next graph replay
        }
    }
}

// ---------------------------------------------------------------------------
extern "C" void kernel_launch(void* const* d_in, const int* in_sizes, int n_in,
                              void* d_out, int out_size) {
    const float* pred = (const float*)d_in[0];
    const float* targ = (const float*)d_in[1];
    const float* mask = (const float*)d_in[2];
    float* out = (float*)d_out;

    dim3 grid(NB1, BATCH);
    pass1_kernel<<<grid, TPB>>>(pred, targ, mask);
    pass3_kernel<<<grid, TPB>>>(pred, targ, out);
}

// round 17
// speedup vs baseline: 1.0479x; 1.0447x over previous
#include <cuda_runtime.h>

#define BATCH 16
#define IMG_H 352
#define IMG_W 1216
#define IMG_HW (IMG_H * IMG_W)
#define TILES_PER_ROW 10                      /* ceil(1216/128): 9 full + 1 half */
#define TILES_PER_IMG (IMG_H * TILES_PER_ROW) /* 3520 */
#define NB1 52
#define TPB 256
#define WPB (TPB / 32)
#define WARPS_PER_IMG (NB1 * WPB)             /* 416 */
#define TOTAL_BLOCKS (NB1 * BATCH)            /* 832 */
#define FULLM 0xffffffffu

// Scratch (no allocations allowed -> device globals)
__device__ float g_part1[BATCH * NB1 * 3];
__device__ float g_scale[2 * BATCH + 1];   // [0..15]=scale_p, [16..31]=scale_t, [32]=total_mask
__device__ float g_part2[BATCH * NB1];
__device__ unsigned int g_cnt1 = 0;
__device__ unsigned int g_cnt2 = 0;

struct SCol { float s0, s1, s2, c; };      // sorted column + original center

__device__ __forceinline__ void cswap(float& a, float& b) {
    float t = fminf(a, b); b = fmaxf(a, b); a = t;
}

__device__ __forceinline__ SCol make_col(float u, float v, float w) {
    SCol r; r.c = v;
    cswap(u, v); cswap(v, w); cswap(u, v);
    r.s0 = u; r.s1 = v; r.s2 = w;
    return r;
}

__device__ __forceinline__ float med3f(float a, float b, float c) {
    return fmaxf(fminf(a, b), fminf(fmaxf(a, b), c));
}

// Exact 3x3 median from 3 column-sorted triples:
// med9 = med3( max(lows), med3(mids), min(highs) )
__device__ __forceinline__ float merge_med(const SCol& A, const SCol& B, const SCol& C) {
    float lo = fmaxf(fmaxf(A.s0, B.s0), C.s0);
    float mi = med3f(A.s1, B.s1, C.s1);
    float hi = fminf(fminf(A.s2, B.s2), C.s2);
    return med3f(lo, mi, hi);
}

// Warp-cooperative: lane l computes contrasts (x - med3x3) of its 4 pixels
// [x0+4l .. x0+4l+3]. Fully coalesced float4 loads; neighbor columns via shfl;
// tile-edge halo columns via predicated scalar loads on lanes 0/31.
__device__ __forceinline__ void contrasts4(const float* __restrict__ row1,
                                           bool up, bool dn, bool active,
                                           int x0, int lane,
                                           bool haloL, bool haloR,
                                           float out[4]) {
    const float* row0 = row1 - IMG_W;
    const float* row2 = row1 + IMG_W;
    const int px0 = x0 + 4 * lane;

    float4 r0 = make_float4(0.f, 0.f, 0.f, 0.f), r1 = r0, r2 = r0;
    if (active) {
        if (up) r0 = __ldg((const float4*)(row0 + px0));
        r1 = __ldg((const float4*)(row1 + px0));
        if (dn) r2 = __ldg((const float4*)(row2 + px0));
    }
    SCol c0 = make_col(r0.x, r1.x, r2.x);
    SCol c1 = make_col(r0.y, r1.y, r2.y);
    SCol c2 = make_col(r0.z, r1.z, r2.z);
    SCol c3 = make_col(r0.w, r1.w, r2.w);

    // halo columns (only the boundary lanes actually load)
    float hu = 0.f, hv = 0.f, hw = 0.f;
    if (lane == 0 && haloL) {
        const int xL = x0 - 1;
        if (up) hu = __ldg(row0 + xL);
        hv = __ldg(row1 + xL);
        if (dn) hw = __ldg(row2 + xL);
    } else if (lane == 31 && haloR) {
        const int xR = x0 + 128;
        if (up) hu = __ldg(row0 + xR);
        hv = __ldg(row1 + xR);
        if (dn) hw = __ldg(row2 + xR);
    }
    SCol hc = make_col(hu, hv, hw);

    // left neighbor sorted column = lane-1's c3 (lane 0 -> halo)
    SCol colL;
    colL.s0 = __shfl_up_sync(FULLM, c3.s0, 1);
    colL.s1 = __shfl_up_sync(FULLM, c3.s1, 1);
    colL.s2 = __shfl_up_sync(FULLM, c3.s2, 1);
    if (lane == 0) { colL.s0 = hc.s0; colL.s1 = hc.s1; colL.s2 = hc.s2; }
    // right neighbor sorted column = lane+1's c0 (lane 31 -> halo)
    SCol colR;
    colR.s0 = __shfl_down_sync(FULLM, c0.s0, 1);
    colR.s1 = __shfl_down_sync(FULLM, c0.s1, 1);
    colR.s2 = __shfl_down_sync(FULLM, c0.s2, 1);
    if (lane == 31) { colR.s0 = hc.s0; colR.s1 = hc.s1; colR.s2 = hc.s2; }

    out[0] = c0.c - merge_med(colL, c0, c1);
    out[1] = c1.c - merge_med(c0, c1, c2);
    out[2] = c2.c - merge_med(c1, c2, c3);
    out[3] = c3.c - merge_med(c2, c3, colR);
}

// ---------------------------------------------------------------------------
// Pass 1 (+ fused pass 2 in last block)
// ---------------------------------------------------------------------------
__global__ void __launch_bounds__(TPB) pass1_kernel(const float* __restrict__ pred,
                                                    const float* __restrict__ targ,
                                                    const float* __restrict__ mask) {
    const int b = blockIdx.y;
    const float* P = pred + (size_t)b * IMG_HW;
    const float* T = targ + (size_t)b * IMG_HW;
    const float* M = mask + (size_t)b * IMG_HW;

    const int lane = threadIdx.x & 31;
    const int wid  = blockIdx.x * WPB + (threadIdx.x >> 5);

    float s_m = 0.f, s_p = 0.f, s_t = 0.f;

    for (int t = wid; t < TILES_PER_IMG; t += WARPS_PER_IMG) {
        const int y  = t / TILES_PER_ROW;
        const int tx = t - y * TILES_PER_ROW;
        const int x0 = tx * 128;
        const int px0 = x0 + 4 * lane;
        const bool active = (px0 < IMG_W);
        const bool up = (y > 0), dn = (y < IMG_H - 1);
        const bool haloL = (tx > 0);
        const bool haloR = (x0 + 128 < IMG_W);

        float pc[4], tc[4];
        contrasts4(P + y * IMG_W, up, dn, active, x0, lane, haloL, haloR, pc);
        contrasts4(T + y * IMG_W, up, dn, active, x0, lane, haloL, haloR, tc);

        float4 m4 = make_float4(0.f, 0.f, 0.f, 0.f);
        if (active) m4 = __ldg((const float4*)(M + y * IMG_W + px0));
        float mv[4] = {m4.x, m4.y, m4.z, m4.w};
#pragma unroll
        for (int k = 0; k < 4; k++) {
            s_m += mv[k];
            s_p = fmaf(mv[k], fabsf(pc[k]), s_p);
            s_t = fmaf(mv[k], fabsf(tc[k]), s_t);
        }
    }

    // block reduce (deterministic)
    __shared__ float shm[3][WPB];
#pragma unroll
    for (int o = 16; o; o >>= 1) {
        s_m += __shfl_down_sync(FULLM, s_m, o);
        s_p += __shfl_down_sync(FULLM, s_p, o);
        s_t += __shfl_down_sync(FULLM, s_t, o);
    }
    const int warp = threadIdx.x >> 5;
    if (lane == 0) { shm[0][warp] = s_m; shm[1][warp] = s_p; shm[2][warp] = s_t; }
    __syncthreads();
    if (threadIdx.x < 32) {
        float vm = (lane < WPB) ? shm[0][lane] : 0.f;
        float vp = (lane < WPB) ? shm[1][lane] : 0.f;
        float vt = (lane < WPB) ? shm[2][lane] : 0.f;
#pragma unroll
        for (int o = 4; o; o >>= 1) {
            vm += __shfl_down_sync(FULLM, vm, o);
            vp += __shfl_down_sync(FULLM, vp, o);
            vt += __shfl_down_sync(FULLM, vt, o);
        }
        if (lane == 0) {
            const int base = (b * NB1 + blockIdx.x) * 3;
            g_part1[base + 0] = vm;
            g_part1[base + 1] = vp;
            g_part1[base + 2] = vt;
        }
    }

    // ---- fused pass 2: last block reduces partials and computes scales ----
    __shared__ bool s_last;
    __syncthreads();
    if (threadIdx.x == 0) {
        __threadfence();
        unsigned v = atomicAdd(&g_cnt1, 1u);
        s_last = (v == TOTAL_BLOCKS - 1);
    }
    __syncthreads();
    if (!s_last) return;
    __threadfence();

    __shared__ double sh[BATCH * 3];
    for (int task = warp; task < BATCH * 3; task += WPB) {
        const int bb = task / 3, c = task - 3 * bb;
        double s = 0.0;
        for (int i = lane; i < NB1; i += 32) s += (double)g_part1[(bb * NB1 + i) * 3 + c];
#pragma unroll
        for (int o = 16; o; o >>= 1) s += __shfl_down_sync(FULLM, s, o);
        if (lane == 0) sh[task] = s;
    }
    __syncthreads();
    if (threadIdx.x < BATCH) {
        const int bb = threadIdx.x;
        double denom = sh[bb * 3 + 0];
        g_scale[bb]         = (float)(denom / sh[bb * 3 + 1]);
        g_scale[BATCH + bb] = (float)(denom / sh[bb * 3 + 2]);
    }
    if (threadIdx.x == TPB - 1) {
        double tm = 0.0;
        for (int bb = 0; bb < BATCH; bb++) tm += sh[bb * 3];
        g_scale[2 * BATCH] = (float)tm;
        g_cnt1 = 0;                  // reset ticket for next graph replay
    }
}

// ---------------------------------------------------------------------------
// Pass 3 (+ fused pass 4 in last block)
// ---------------------------------------------------------------------------
__global__ void __launch_bounds__(TPB) pass3_kernel(const float* __restrict__ pred,
                                                    const float* __restrict__ targ,
                                                    float* __restrict__ out) {
    const int b = blockIdx.y;
    const float* P = pred + (size_t)b * IMG_HW;
    const float* T = targ + (size_t)b * IMG_HW;
    const float sp = g_scale[b];
    const float st = g_scale[BATCH + b];

    const int lane = threadIdx.x & 31;
    const int wid  = blockIdx.x * WPB + (threadIdx.x >> 5);

    float s = 0.f;

    for (int t = wid; t < TILES_PER_IMG; t += WARPS_PER_IMG) {
        const int y  = t / TILES_PER_ROW;
        const int tx = t - y * TILES_PER_ROW;
        const int x0 = tx * 128;
        const int px0 = x0 + 4 * lane;
        const bool active = (px0 < IMG_W);
        const bool up = (y > 0), dn = (y < IMG_H - 1);
        const bool haloL = (tx > 0);
        const bool haloR = (x0 + 128 < IMG_W);

        float pc[4], tc[4];
        contrasts4(P + y * IMG_W, up, dn, active, x0, lane, haloL, haloR, pc);
        contrasts4(T + y * IMG_W, up, dn, active, x0, lane, haloL, haloR, tc);
#pragma unroll
        for (int k = 0; k < 4; k++)
            s += fabsf(fmaf(pc[k], sp, -(tc[k] * st)));
    }

    __shared__ float shm[WPB];
#pragma unroll
    for (int o = 16; o; o >>= 1) s += __shfl_down_sync(FULLM, s, o);
    const int warp = threadIdx.x >> 5;
    if (lane == 0) shm[warp] = s;
    __syncthreads();
    if (threadIdx.x < 32) {
        float v = (lane < WPB) ? shm[lane] : 0.f;
#pragma unroll
        for (int o = 4; o; o >>= 1) v += __shfl_down_sync(FULLM, v, o);
        if (lane == 0) g_part2[b * NB1 + blockIdx.x] = v;
    }

    // ---- fused pass 4: last block reduces loss partials to the scalar ----
    __shared__ bool s_last;
    __syncthreads();
    if (threadIdx.x == 0) {
        __threadfence();
        unsigned v = atomicAdd(&g_cnt2, 1u);
        s_last = (v == TOTAL_BLOCKS - 1);
    }
    __syncthreads();
    if (!s_last) return;
    __threadfence();

    double sd = 0.0;
    for (int i = threadIdx.x; i < BATCH * NB1; i += TPB) sd += (double)g_part2[i];
#pragma unroll
    for (int o = 16; o; o >>= 1) sd += __shfl_down_sync(FULLM, sd, o);
    __shared__ double shd[WPB];
    if (lane == 0) shd[warp] = sd;
    __syncthreads();
    if (threadIdx.x < 32) {
        double v = (lane < WPB) ? shd[lane] : 0.0;
#pragma unroll
        for (int o = 4; o; o >>= 1) v += __shfl_down_sync(FULLM, v, o);
        if (lane == 0) {
            out[0] = (float)(v / (double)g_scale[2 * BATCH]);
            g_cnt2 = 0;              // reset ticket for next graph replay
        }
    }
}

// ---------------------------------------------------------------------------
extern "C" void kernel_launch(void* const* d_in, const int* in_sizes, int n_in,
                              void* d_out, int out_size) {
    const float* pred = (const float*)d_in[0];
    const float* targ = (const float*)d_in[1];
    const float* mask = (const float*)d_in[2];
    float* out = (float*)d_out;

    dim3 grid(NB1, BATCH);
    pass1_kernel<<<grid, TPB>>>(pred, targ, mask);
    pass3_kernel<<<grid, TPB>>>(pred, targ, out);
}